// round 13
// baseline (speedup 1.0000x reference)
#include <cuda_runtime.h>
#include <cuda_bf16.h>
#include <math.h>

#define NG 2048
#define IMW 128
#define IMH 128
#define HW (IMW*IMH)
#define GRID 128
#define NTHREADS 256

#define TANFOVX 0.5f
#define TANFOVY 0.5f
#define FOCAL_X (IMW / (2.0f * TANFOVX))   // 128
#define FOCAL_Y (IMH / (2.0f * TANFOVY))   // 128
#define FARZ 1e10f

#define SH_C0 0.28209479177387814f
#define SH_C1 0.4886025119029199f
#define SH_C2_0 1.0925484305920792f
#define SH_C2_1 (-1.0925484305920792f)
#define SH_C2_2 0.31539156525252005f
#define SH_C2_3 (-1.0925484305920792f)
#define SH_C2_4 0.5462742152960396f
#define SH_C3_0 (-0.5900435899266435f)
#define SH_C3_1 2.890611442640554f
#define SH_C3_2 (-0.4570457994644657f)
#define SH_C3_3 0.3731763325901154f
#define SH_C3_4 (-0.4570457994644657f)
#define SH_C3_5 1.445305721320277f
#define SH_C3_6 (-0.5900435899266435f)

// Unsorted packed records
__device__ float4 g_upack0[NG];  // px, py, na(-0.5ca), nb(-cb)
__device__ float4 g_upack1[NG];  // nc(-0.5cc), op, cr, cg
__device__ float4 g_upack2[NG];  // cb(blue), invd, rad, id
__device__ float  g_depth[NG];
// Depth-sorted packed records
__device__ float4 g_pack0[NG];
__device__ float4 g_pack1[NG];
__device__ float4 g_pack2[NG];

// Monotone ticket grid barrier (replay-safe: target derived from ticket).
__device__ unsigned int g_bar_ctr = 0;

__device__ __forceinline__ void grid_barrier()
{
    __syncthreads();
    if (threadIdx.x == 0) {
        __threadfence();
        unsigned int ticket = atomicAdd(&g_bar_ctr, 1u);
        unsigned int target = (ticket / GRID + 1u) * GRID;
        unsigned int v;
        do {
            asm volatile("ld.acquire.gpu.u32 %0, [%1];" : "=r"(v) : "l"(&g_bar_ctr));
        } while (v < target);
    }
    __syncthreads();
}

#define CHUNK 256
#define NCHUNK (NG / CHUNK)   // 8

struct RasterSmem {
    float4 A[CHUNK + 1];      // +1: prefetch overrun pad
    float4 B[CHUNK + 1];
    float4 C[CHUNK + 1];
    int    w[8];              // per-warp keep counts
    // per-pixel merge slots (hi half partials) + running T broadcast
    float  hcr[128], hcg[128], hcb[128], hid[128];
    float  hT[128], hmw[128], hbt[128];
    float  sT[128];
};

__global__ void __launch_bounds__(NTHREADS) fused_kernel(
    const float* __restrict__ means3D,
    const float* __restrict__ opacities,
    const float* __restrict__ dc,
    const float* __restrict__ shs,
    const float* __restrict__ scales,
    const float* __restrict__ rotations,
    const float* __restrict__ Vm,
    const float* __restrict__ Pm,
    float* __restrict__ out)
{
    __shared__ float sd[NG];          // phase 2 (8KB)
    __shared__ RasterSmem rs;         // phase 3 (~16.5KB)

    int tid  = threadIdx.x;
    int warp = tid >> 5;
    int lane = tid & 31;

    // ========================================================
    // Phase 1: preprocess. threads 0..15 own one gaussian each
    // ========================================================
    if (tid < 16) {
        int n = blockIdx.x * 16 + tid;

        float m0 = means3D[3*n+0], m1 = means3D[3*n+1], m2 = means3D[3*n+2];

        float pv0 = m0*Vm[0] + m1*Vm[4] + m2*Vm[8]  + Vm[12];
        float pv1 = m0*Vm[1] + m1*Vm[5] + m2*Vm[9]  + Vm[13];
        float pv2 = m0*Vm[2] + m1*Vm[6] + m2*Vm[10] + Vm[14];

        float ph0 = m0*Pm[0] + m1*Pm[4] + m2*Pm[8]  + Pm[12];
        float ph1 = m0*Pm[1] + m1*Pm[5] + m2*Pm[9]  + Pm[13];
        float ph3 = m0*Pm[3] + m1*Pm[7] + m2*Pm[11] + Pm[15];
        float invw = 1.0f / (ph3 + 1e-7f);
        float px = ((ph0*invw + 1.0f) * IMW - 1.0f) * 0.5f;
        float py = ((ph1*invw + 1.0f) * IMH - 1.0f) * 0.5f;

        float tz = pv2;
        float limx = 1.3f * TANFOVX, limy = 1.3f * TANFOVY;
        float tx = fminf(fmaxf(pv0 / tz, -limx), limx) * tz;
        float ty = fminf(fmaxf(pv1 / tz, -limy), limy) * tz;

        float qr = rotations[4*n+0], qx = rotations[4*n+1],
              qy = rotations[4*n+2], qz = rotations[4*n+3];
        float R00 = 1.f - 2.f*(qy*qy + qz*qz);
        float R01 = 2.f*(qx*qy - qr*qz);
        float R02 = 2.f*(qx*qz + qr*qy);
        float R10 = 2.f*(qx*qy + qr*qz);
        float R11 = 1.f - 2.f*(qx*qx + qz*qz);
        float R12 = 2.f*(qy*qz - qr*qx);
        float R20 = 2.f*(qx*qz - qr*qy);
        float R21 = 2.f*(qy*qz + qr*qx);
        float R22 = 1.f - 2.f*(qx*qx + qy*qy);

        float s0 = scales[3*n+0], s1 = scales[3*n+1], s2 = scales[3*n+2];
        float M00=R00*s0, M01=R01*s1, M02=R02*s2;
        float M10=R10*s0, M11=R11*s1, M12=R12*s2;
        float M20=R20*s0, M21=R21*s1, M22=R22*s2;
        float S00 = M00*M00 + M01*M01 + M02*M02;
        float S01 = M00*M10 + M01*M11 + M02*M12;
        float S02 = M00*M20 + M01*M21 + M02*M22;
        float S11 = M10*M10 + M11*M11 + M12*M12;
        float S12 = M10*M20 + M11*M21 + M12*M22;
        float S22 = M20*M20 + M21*M21 + M22*M22;

        float itz = 1.0f / tz;
        float J00 = FOCAL_X * itz;
        float J02 = -FOCAL_X * tx * itz * itz;
        float J11 = FOCAL_Y * itz;
        float J12 = -FOCAL_Y * ty * itz * itz;

        float T00 = J00*Vm[0] + J02*Vm[2];
        float T01 = J00*Vm[4] + J02*Vm[6];
        float T02 = J00*Vm[8] + J02*Vm[10];
        float T10 = J11*Vm[1] + J12*Vm[2];
        float T11 = J11*Vm[5] + J12*Vm[6];
        float T12 = J11*Vm[9] + J12*Vm[10];

        float A00 = T00*S00 + T01*S01 + T02*S02;
        float A01 = T00*S01 + T01*S11 + T02*S12;
        float A02 = T00*S02 + T01*S12 + T02*S22;
        float B00 = T10*S00 + T11*S01 + T12*S02;
        float B01 = T10*S01 + T11*S11 + T12*S12;
        float B02 = T10*S02 + T11*S12 + T12*S22;

        float cov00 = A00*T00 + A01*T01 + A02*T02;
        float cov01 = A00*T10 + A01*T11 + A02*T12;
        float cov11 = B00*T10 + B01*T11 + B02*T12;

        float a = cov00 + 0.3f;
        float b = cov01;
        float c = cov11 + 0.3f;
        float det = a*c - b*b;
        bool valid = (tz > 0.2f) && (det > 0.0f);
        float det_inv = (det > 0.0f) ? (1.0f / det) : 0.0f;

        float mid = 0.5f * (a + c);
        float lam1 = mid + sqrtf(fmaxf(0.1f, mid*mid - det));
        float radius = ceilf(3.0f * sqrtf(lam1));

        float invn = rsqrtf(m0*m0 + m1*m1 + m2*m2);
        float dX = m0*invn, dY = m1*invn, dZ = m2*invn;
        float xx = dX*dX, yy = dY*dY, zz = dZ*dZ;
        float xy = dX*dY, yz = dY*dZ, xz = dX*dZ;

        float col[3];
        #pragma unroll
        for (int ch = 0; ch < 3; ch++) {
            const float* sh = shs + (size_t)n*45 + ch;
            float res = SH_C0 * dc[3*n + ch];
            res += -SH_C1 * dY * sh[0*3] + SH_C1 * dZ * sh[1*3] - SH_C1 * dX * sh[2*3];
            res += SH_C2_0 * xy * sh[3*3] + SH_C2_1 * yz * sh[4*3]
                 + SH_C2_2 * (2.f*zz - xx - yy) * sh[5*3]
                 + SH_C2_3 * xz * sh[6*3] + SH_C2_4 * (xx - yy) * sh[7*3];
            res += SH_C3_0 * dY * (3.f*xx - yy) * sh[8*3]
                 + SH_C3_1 * xy * dZ * sh[9*3]
                 + SH_C3_2 * dY * (4.f*zz - xx - yy) * sh[10*3]
                 + SH_C3_3 * dZ * (2.f*zz - 3.f*xx - 3.f*yy) * sh[11*3]
                 + SH_C3_4 * dX * (4.f*zz - xx - yy) * sh[12*3]
                 + SH_C3_5 * dZ * (xx - yy) * sh[13*3]
                 + SH_C3_6 * dX * (xx - 3.f*yy) * sh[14*3];
            col[ch] = fmaxf(res + 0.5f, 0.0f);
        }

        float depth = valid ? tz : FARZ;
        float rad   = valid ? radius : 0.0f;

        float ca = c * det_inv, cbq = -b * det_inv, ccq = a * det_inv;
        g_upack0[n] = make_float4(px, py, -0.5f * ca, -cbq);
        g_upack1[n] = make_float4(-0.5f * ccq, opacities[n], col[0], col[1]);
        g_upack2[n] = make_float4(col[2], 1.0f / depth, rad, (float)n);
        g_depth[n]  = depth;

        out[5*HW + n] = rad;   // radii
    }

    grid_barrier();

    // ========================================================
    // Phase 2: stable rank-count argsort + scatter.
    // 16 gaussians/block over 8 warps -> 2 rounds each.
    // ========================================================
    #pragma unroll
    for (int i = tid; i < NG; i += NTHREADS) sd[i] = g_depth[i];
    __syncthreads();

    #pragma unroll
    for (int r = 0; r < 2; r++) {
        int gi = blockIdx.x * 16 + warp * 2 + r;
        float di = sd[gi];
        int cnt = 0;
        #pragma unroll 8
        for (int j = lane; j < NG; j += 32) {
            float dj = sd[j];
            cnt += (dj < di) || (dj == di && j < gi);
        }
        #pragma unroll
        for (int o = 16; o > 0; o >>= 1) cnt += __shfl_down_sync(0xffffffffu, cnt, o);
        if (lane == 0) {
            g_pack0[cnt] = g_upack0[gi];
            g_pack1[cnt] = g_upack1[gi];
            g_pack2[cnt] = g_upack2[gi];
        }
    }

    grid_barrier();

    // ========================================================
    // Phase 3: raster, 16x8 tile, two threads per pixel.
    // Pixel p owned by threads p (lo) and p+128 (hi): lo blends
    // survivors [0,h), hi blends [h,total) with local state;
    // lo folds hi's partials via exact segment composition.
    // All 8 warps active during blend (2/SMSP).
    // ========================================================
    int bx = blockIdx.x & 7;
    int by = blockIdx.x >> 3;

    float tx0 = (float)(bx * 16);
    float tx1 = tx0 + 15.0f;
    float ty0 = (float)(by * 8);
    float ty1 = ty0 + 7.0f;

    int p  = tid & 127;              // pixel index within tile
    bool hiHalf = (tid >= 128);
    int lx = p & 15;
    int ly = p >> 4;
    float fx = (float)(bx * 16 + lx);
    float fy = (float)(by * 8 + ly);

    // running state (meaningful in lo thread only)
    float Scr = 0.f, Scg = 0.f, Scb = 0.f, Sid = 0.f;
    float ST = 1.0f, Smw = 0.f, Sbt = -1.0f;

    if (!hiHalf) rs.sT[p] = 1.0f;

    // prefetch chunk 0 record (one per thread)
    float4 a0 = g_pack0[tid], b0 = g_pack1[tid], c0 = g_pack2[tid];
    __syncthreads();   // sT visible

    for (int c = 0; c < NCHUNK; c++) {
        // ---- cull + compact current chunk (all threads) ----
        float rr = c0.z;
        bool keep = (rr > 0.0f) &&
                    (a0.x >= tx0 - rr) && (a0.x <= tx1 + rr) &&
                    (a0.y >= ty0 - rr) && (a0.y <= ty1 + rr);
        unsigned int m = __ballot_sync(0xffffffffu, keep);
        if (lane == 0) rs.w[warp] = __popc(m);
        __syncthreads();

        int off = 0, total = 0;
        #pragma unroll
        for (int w = 0; w < 8; w++) {
            int cw = rs.w[w];
            if (w < warp) off += cw;
            total += cw;
        }
        if (keep) {
            int pos = off + __popc(m & ((1u << lane) - 1u));
            rs.A[pos] = a0; rs.B[pos] = b0; rs.C[pos] = c0;
        }
        __syncthreads();

        // ---- prefetch next chunk into registers (hidden under blend) ----
        if (c + 1 < NCHUNK) {
            int j = (c + 1) * CHUNK + tid;
            a0 = g_pack0[j]; b0 = g_pack1[j]; c0 = g_pack2[j];
        }

        // ---- blend local half with fresh local state ----
        int h     = (total + 1) >> 1;
        int gbeg  = hiHalf ? h : 0;
        int gend  = hiHalf ? total : h;

        float lcr = 0.f, lcg = 0.f, lcb = 0.f, lid = 0.f;
        float lT = 1.0f, lmw = 0.f, lbt = -1.0f;

        float liveT = rs.sT[p];
        if (liveT >= 1e-4f && gend > gbeg) {
            float4 A = rs.A[gbeg];
            float4 B = rs.B[gbeg];
            float4 C = rs.C[gbeg];
            for (int g = gbeg; g < gend; g++) {
                float4 A2 = rs.A[g + 1];   // pad slot makes overrun safe
                float4 B2 = rs.B[g + 1];
                float4 C2 = rs.C[g + 1];

                float dx = fx - A.x;
                float dy = fy - A.y;
                float r  = C.z;
                float power = fmaf(A.z, dx*dx, fmaf(B.x, dy*dy, A.w*(dx*dy)));
                float alpha = fminf(0.99f, B.y * __expf(power));
                bool ok = (fabsf(dx) <= r) & (fabsf(dy) <= r) &
                          (power <= 0.0f) & (alpha >= (1.0f/255.0f));
                float a = ok ? alpha : 0.0f;
                float w = a * lT;
                lcr += w * B.z;
                lcg += w * B.w;
                lcb += w * C.x;
                lid += w * C.y;
                bool better = (w > lmw);
                lmw = better ? w : lmw;
                lbt = better ? C.w : lbt;
                lT  = lT * (1.0f - a);

                A = A2; B = B2; C = C2;
            }
        }

        // ---- pair merge: hi publishes, lo composes ----
        if (hiHalf) {
            rs.hcr[p] = lcr; rs.hcg[p] = lcg; rs.hcb[p] = lcb; rs.hid[p] = lid;
            rs.hT[p] = lT; rs.hmw[p] = lmw; rs.hbt[p] = lbt;
        }
        __syncthreads();

        bool done;
        if (!hiHalf) {
            // combined chunk contribution = lo + loT*hi
            float ccr = lcr + lT * rs.hcr[p];
            float ccg = lcg + lT * rs.hcg[p];
            float ccb = lcb + lT * rs.hcb[p];
            float cid = lid + lT * rs.hid[p];
            float hmwS = lT * rs.hmw[p];
            bool hiWins = (hmwS > lmw);
            float cmw = hiWins ? hmwS : lmw;
            float cbt = hiWins ? rs.hbt[p] : lbt;
            float cT  = lT * rs.hT[p];

            // fold into running state
            Scr += ST * ccr;
            Scg += ST * ccg;
            Scb += ST * ccb;
            Sid += ST * cid;
            float cand = ST * cmw;
            bool better = (cand > Smw);
            Smw = better ? cand : Smw;
            Sbt = better ? cbt : Sbt;
            ST  = ST * cT;

            rs.sT[p] = ST;
            done = (ST < 1e-4f);
        } else {
            done = true;   // hi votes done; lo's vote decides
        }
        if (__syncthreads_and(done)) break;
    }

    if (!hiHalf) {
        int pix = (by * 8 + ly) * IMW + (bx * 16 + lx);
        out[0*HW + pix] = Scr;
        out[1*HW + pix] = Scg;
        out[2*HW + pix] = Scb;
        out[3*HW + pix] = Sid;
        out[4*HW + pix] = (Smw > 0.0f) ? Sbt : -1.0f;
    }
}

extern "C" void kernel_launch(void* const* d_in, const int* in_sizes, int n_in,
                              void* d_out, int out_size)
{
    (void)in_sizes; (void)n_in; (void)out_size;
    const float* means3D   = (const float*)d_in[0];
    const float* opacities = (const float*)d_in[2];
    const float* dc        = (const float*)d_in[3];
    const float* shs       = (const float*)d_in[4];
    const float* scales    = (const float*)d_in[5];
    const float* rotations = (const float*)d_in[6];
    const float* viewm     = (const float*)d_in[7];
    const float* projm     = (const float*)d_in[8];
    float* out = (float*)d_out;

    fused_kernel<<<GRID, NTHREADS>>>(means3D, opacities, dc, shs, scales,
                                     rotations, viewm, projm, out);
}

// round 14
// speedup vs baseline: 1.0714x; 1.0714x over previous
#include <cuda_runtime.h>
#include <cuda_bf16.h>
#include <math.h>

#define NG 2048
#define IMW 128
#define IMH 128
#define HW (IMW*IMH)
#define GRID 128
#define NTHREADS 256

#define TANFOVX 0.5f
#define TANFOVY 0.5f
#define FOCAL_X (IMW / (2.0f * TANFOVX))   // 128
#define FOCAL_Y (IMH / (2.0f * TANFOVY))   // 128
#define FARZ 1e10f

#define SH_C0 0.28209479177387814f
#define SH_C1 0.4886025119029199f
#define SH_C2_0 1.0925484305920792f
#define SH_C2_1 (-1.0925484305920792f)
#define SH_C2_2 0.31539156525252005f
#define SH_C2_3 (-1.0925484305920792f)
#define SH_C2_4 0.5462742152960396f
#define SH_C3_0 (-0.5900435899266435f)
#define SH_C3_1 2.890611442640554f
#define SH_C3_2 (-0.4570457994644657f)
#define SH_C3_3 0.3731763325901154f
#define SH_C3_4 (-0.4570457994644657f)
#define SH_C3_5 1.445305721320277f
#define SH_C3_6 (-0.5900435899266435f)

// Unsorted packed records
__device__ float4 g_upack0[NG];  // px, py, na(-0.5ca), nb(-cb)
__device__ float4 g_upack1[NG];  // nc(-0.5cc), op, cr, cg
__device__ float4 g_upack2[NG];  // cb(blue), invd, rad, id
__device__ float  g_depth[NG];
// Depth-sorted packed records
__device__ float4 g_pack0[NG];
__device__ float4 g_pack1[NG];
__device__ float4 g_pack2[NG];

// Monotone ticket grid barrier (replay-safe: target derived from ticket).
__device__ unsigned int g_bar_ctr = 0;

__device__ __forceinline__ void grid_barrier()
{
    __syncthreads();
    if (threadIdx.x == 0) {
        __threadfence();
        unsigned int ticket = atomicAdd(&g_bar_ctr, 1u);
        unsigned int target = (ticket / GRID + 1u) * GRID;
        unsigned int v;
        do {
            asm volatile("ld.acquire.gpu.u32 %0, [%1];" : "=r"(v) : "l"(&g_bar_ctr));
        } while (v < target);
    }
    __syncthreads();
}

#define CHUNK 256
#define NCHUNK (NG / CHUNK)   // 8

struct RasterSmem {
    float4 A[2][CHUNK + 1];   // +1: prefetch overrun pad (never computed)
    float4 B[2][CHUNK + 1];
    float4 C[2][CHUNK + 1];
    int    w[2][8];           // per-producer-warp keep counts (lo 4, hi 4)
};

__global__ void __launch_bounds__(NTHREADS) fused_kernel(
    const float* __restrict__ means3D,
    const float* __restrict__ opacities,
    const float* __restrict__ dc,
    const float* __restrict__ shs,
    const float* __restrict__ scales,
    const float* __restrict__ rotations,
    const float* __restrict__ Vm,
    const float* __restrict__ Pm,
    float* __restrict__ out)
{
    __shared__ float sd[NG];          // phase 2 (8KB)
    __shared__ RasterSmem rs;         // phase 3 (~24KB)

    int tid  = threadIdx.x;
    int warp = tid >> 5;
    int lane = tid & 31;

    // ========================================================
    // Phase 1: preprocess, split across roles.
    //   threads 0..15 : geometry for gaussian blockIdx*16+tid
    //   threads 16..63: SH color, 3 threads/gaussian (1/channel)
    // Disjoint scalar writes into the packed records; published
    // by the grid barrier (no extra sync needed).
    // ========================================================
    if (tid < 16) {
        int n = blockIdx.x * 16 + tid;

        float m0 = means3D[3*n+0], m1 = means3D[3*n+1], m2 = means3D[3*n+2];

        float pv0 = m0*Vm[0] + m1*Vm[4] + m2*Vm[8]  + Vm[12];
        float pv1 = m0*Vm[1] + m1*Vm[5] + m2*Vm[9]  + Vm[13];
        float pv2 = m0*Vm[2] + m1*Vm[6] + m2*Vm[10] + Vm[14];

        float ph0 = m0*Pm[0] + m1*Pm[4] + m2*Pm[8]  + Pm[12];
        float ph1 = m0*Pm[1] + m1*Pm[5] + m2*Pm[9]  + Pm[13];
        float ph3 = m0*Pm[3] + m1*Pm[7] + m2*Pm[11] + Pm[15];
        float invw = 1.0f / (ph3 + 1e-7f);
        float px = ((ph0*invw + 1.0f) * IMW - 1.0f) * 0.5f;
        float py = ((ph1*invw + 1.0f) * IMH - 1.0f) * 0.5f;

        float tz = pv2;
        float limx = 1.3f * TANFOVX, limy = 1.3f * TANFOVY;
        float tx = fminf(fmaxf(pv0 / tz, -limx), limx) * tz;
        float ty = fminf(fmaxf(pv1 / tz, -limy), limy) * tz;

        float qr = rotations[4*n+0], qx = rotations[4*n+1],
              qy = rotations[4*n+2], qz = rotations[4*n+3];
        float R00 = 1.f - 2.f*(qy*qy + qz*qz);
        float R01 = 2.f*(qx*qy - qr*qz);
        float R02 = 2.f*(qx*qz + qr*qy);
        float R10 = 2.f*(qx*qy + qr*qz);
        float R11 = 1.f - 2.f*(qx*qx + qz*qz);
        float R12 = 2.f*(qy*qz - qr*qx);
        float R20 = 2.f*(qx*qz - qr*qy);
        float R21 = 2.f*(qy*qz + qr*qx);
        float R22 = 1.f - 2.f*(qx*qx + qy*qy);

        float s0 = scales[3*n+0], s1 = scales[3*n+1], s2 = scales[3*n+2];
        float M00=R00*s0, M01=R01*s1, M02=R02*s2;
        float M10=R10*s0, M11=R11*s1, M12=R12*s2;
        float M20=R20*s0, M21=R21*s1, M22=R22*s2;
        float S00 = M00*M00 + M01*M01 + M02*M02;
        float S01 = M00*M10 + M01*M11 + M02*M12;
        float S02 = M00*M20 + M01*M21 + M02*M22;
        float S11 = M10*M10 + M11*M11 + M12*M12;
        float S12 = M10*M20 + M11*M21 + M12*M22;
        float S22 = M20*M20 + M21*M21 + M22*M22;

        float itz = 1.0f / tz;
        float J00 = FOCAL_X * itz;
        float J02 = -FOCAL_X * tx * itz * itz;
        float J11 = FOCAL_Y * itz;
        float J12 = -FOCAL_Y * ty * itz * itz;

        float T00 = J00*Vm[0] + J02*Vm[2];
        float T01 = J00*Vm[4] + J02*Vm[6];
        float T02 = J00*Vm[8] + J02*Vm[10];
        float T10 = J11*Vm[1] + J12*Vm[2];
        float T11 = J11*Vm[5] + J12*Vm[6];
        float T12 = J11*Vm[9] + J12*Vm[10];

        float A00 = T00*S00 + T01*S01 + T02*S02;
        float A01 = T00*S01 + T01*S11 + T02*S12;
        float A02 = T00*S02 + T01*S12 + T02*S22;
        float B00 = T10*S00 + T11*S01 + T12*S02;
        float B01 = T10*S01 + T11*S11 + T12*S12;
        float B02 = T10*S02 + T11*S12 + T12*S22;

        float cov00 = A00*T00 + A01*T01 + A02*T02;
        float cov01 = A00*T10 + A01*T11 + A02*T12;
        float cov11 = B00*T10 + B01*T11 + B02*T12;

        float a = cov00 + 0.3f;
        float b = cov01;
        float c = cov11 + 0.3f;
        float det = a*c - b*b;
        bool valid = (tz > 0.2f) && (det > 0.0f);
        float det_inv = (det > 0.0f) ? (1.0f / det) : 0.0f;

        float mid = 0.5f * (a + c);
        float lam1 = mid + sqrtf(fmaxf(0.1f, mid*mid - det));
        float radius = ceilf(3.0f * sqrtf(lam1));

        float depth = valid ? tz : FARZ;
        float rad   = valid ? radius : 0.0f;

        float ca = c * det_inv, cbq = -b * det_inv, ccq = a * det_inv;
        g_upack0[n] = make_float4(px, py, -0.5f * ca, -cbq);
        float* u1 = (float*)&g_upack1[n];
        u1[0] = -0.5f * ccq;
        u1[1] = opacities[n];
        float* u2 = (float*)&g_upack2[n];
        u2[1] = 1.0f / depth;
        u2[2] = rad;
        u2[3] = (float)n;
        g_depth[n]  = depth;

        out[5*HW + n] = rad;   // radii
    } else if (tid < 64) {
        int t  = tid - 16;
        int g  = t / 3;              // 0..15
        int ch = t - g * 3;          // 0..2
        int n  = blockIdx.x * 16 + g;

        float m0 = means3D[3*n+0], m1 = means3D[3*n+1], m2 = means3D[3*n+2];
        float invn = rsqrtf(m0*m0 + m1*m1 + m2*m2);
        float dX = m0*invn, dY = m1*invn, dZ = m2*invn;
        float xx = dX*dX, yy = dY*dY, zz = dZ*dZ;
        float xy = dX*dY, yz = dY*dZ, xz = dX*dZ;

        const float* sh = shs + (size_t)n*45 + ch;
        float res = SH_C0 * dc[3*n + ch];
        res += -SH_C1 * dY * sh[0*3] + SH_C1 * dZ * sh[1*3] - SH_C1 * dX * sh[2*3];
        res += SH_C2_0 * xy * sh[3*3] + SH_C2_1 * yz * sh[4*3]
             + SH_C2_2 * (2.f*zz - xx - yy) * sh[5*3]
             + SH_C2_3 * xz * sh[6*3] + SH_C2_4 * (xx - yy) * sh[7*3];
        res += SH_C3_0 * dY * (3.f*xx - yy) * sh[8*3]
             + SH_C3_1 * xy * dZ * sh[9*3]
             + SH_C3_2 * dY * (4.f*zz - xx - yy) * sh[10*3]
             + SH_C3_3 * dZ * (2.f*zz - 3.f*xx - 3.f*yy) * sh[11*3]
             + SH_C3_4 * dX * (4.f*zz - xx - yy) * sh[12*3]
             + SH_C3_5 * dZ * (xx - yy) * sh[13*3]
             + SH_C3_6 * dX * (xx - 3.f*yy) * sh[14*3];
        float col = fmaxf(res + 0.5f, 0.0f);

        if (ch == 0)      ((float*)&g_upack1[n])[2] = col;  // cr
        else if (ch == 1) ((float*)&g_upack1[n])[3] = col;  // cg
        else              ((float*)&g_upack2[n])[0] = col;  // cb
    }

    grid_barrier();

    // ========================================================
    // Phase 2: stable rank-count argsort + scatter.
    // 16 gaussians/block over 8 warps -> 2 rounds each.
    // ========================================================
    #pragma unroll
    for (int i = tid; i < NG; i += NTHREADS) sd[i] = g_depth[i];
    __syncthreads();

    #pragma unroll
    for (int r = 0; r < 2; r++) {
        int gi = blockIdx.x * 16 + warp * 2 + r;
        float di = sd[gi];
        int cnt = 0;
        #pragma unroll 8
        for (int j = lane; j < NG; j += 32) {
            float dj = sd[j];
            cnt += (dj < di) || (dj == di && j < gi);
        }
        #pragma unroll
        for (int o = 16; o > 0; o >>= 1) cnt += __shfl_down_sync(0xffffffffu, cnt, o);
        if (lane == 0) {
            g_pack0[cnt] = g_upack0[gi];
            g_pack1[cnt] = g_upack1[gi];
            g_pack2[cnt] = g_upack2[gi];
        }
    }

    grid_barrier();

    // ========================================================
    // Phase 3: warp-specialized raster (R10, unchanged).
    // Warps 0-3: consumers; warps 4-7: producers.
    // ========================================================
    bool producer = (tid >= 128);
    int bx = blockIdx.x & 7;
    int by = blockIdx.x >> 3;

    float tx0 = (float)(bx * 16);
    float tx1 = tx0 + 15.0f;
    float ty0 = (float)(by * 8);
    float ty1 = ty0 + 7.0f;

    int lx = tid & 15;
    int ly = (tid >> 4) & 7;
    int x = bx * 16 + lx;
    int y = by * 8 + ly;
    float fx = (float)x, fy = (float)y;

    float T = producer ? 0.0f : 1.0f;   // producers always vote "done"
    float cr = 0.f, cg = 0.f, cb = 0.f, invd = 0.f;
    float maxw = 0.f;
    float best = -1.0f;

    int ptid = tid - 128;
    int pw   = warp - 4;

    auto fill = [&](int c, int b) {
        int i0 = c * CHUNK + ptid;
        int i1 = i0 + 128;
        float4 a0 = g_pack0[i0], b0 = g_pack1[i0], c0 = g_pack2[i0];
        float4 a1 = g_pack0[i1], b1 = g_pack1[i1], c1 = g_pack2[i1];

        float r0 = c0.z, r1 = c1.z;
        bool k0 = (r0 > 0.0f) && (a0.x >= tx0 - r0) && (a0.x <= tx1 + r0) &&
                                 (a0.y >= ty0 - r0) && (a0.y <= ty1 + r0);
        bool k1 = (r1 > 0.0f) && (a1.x >= tx0 - r1) && (a1.x <= tx1 + r1) &&
                                 (a1.y >= ty0 - r1) && (a1.y <= ty1 + r1);

        unsigned int m0 = __ballot_sync(0xffffffffu, k0);
        unsigned int m1 = __ballot_sync(0xffffffffu, k1);
        if (lane == 0) { rs.w[b][pw] = __popc(m0); rs.w[b][4 + pw] = __popc(m1); }
        asm volatile("bar.sync 8, 128;" ::: "memory");   // producers only

        int off0 = 0, cnt0 = 0, off1 = 0;
        #pragma unroll
        for (int w = 0; w < 4; w++) {
            int c_lo = rs.w[b][w], c_hi = rs.w[b][4 + w];
            if (w < pw) { off0 += c_lo; off1 += c_hi; }
            cnt0 += c_lo;
        }
        if (k0) {
            int pos = off0 + __popc(m0 & ((1u << lane) - 1u));
            rs.A[b][pos] = a0; rs.B[b][pos] = b0; rs.C[b][pos] = c0;
        }
        if (k1) {
            int pos = cnt0 + off1 + __popc(m1 & ((1u << lane) - 1u));
            rs.A[b][pos] = a1; rs.B[b][pos] = b1; rs.C[b][pos] = c1;
        }
    };

    if (producer) fill(0, 0);
    __syncthreads();

    for (int c = 0; c < NCHUNK; c++) {
        int buf = c & 1;

        if (producer) {
            if (c + 1 < NCHUNK) fill(c + 1, buf ^ 1);
        } else {
            int total = rs.w[buf][0] + rs.w[buf][1] + rs.w[buf][2] + rs.w[buf][3]
                      + rs.w[buf][4] + rs.w[buf][5] + rs.w[buf][6] + rs.w[buf][7];
            if (T >= 1e-4f && total > 0) {
                // software-pipelined blend: prefetch g+1 before computing g
                float4 A = rs.A[buf][0];
                float4 B = rs.B[buf][0];
                float4 C = rs.C[buf][0];
                for (int g = 0; g < total; g++) {
                    float4 A2 = rs.A[buf][g + 1];   // pad slot: safe overrun
                    float4 B2 = rs.B[buf][g + 1];
                    float4 C2 = rs.C[buf][g + 1];

                    float dx = fx - A.x;
                    float dy = fy - A.y;
                    float r  = C.z;
                    float power = fmaf(A.z, dx*dx, fmaf(B.x, dy*dy, A.w*(dx*dy)));
                    float alpha = fminf(0.99f, B.y * __expf(power));
                    bool ok = (fabsf(dx) <= r) & (fabsf(dy) <= r) &
                              (power <= 0.0f) & (alpha >= (1.0f/255.0f));
                    float a = ok ? alpha : 0.0f;
                    float w = a * T;
                    cr   += w * B.z;
                    cg   += w * B.w;
                    cb   += w * C.x;
                    invd += w * C.y;
                    bool better = (w > maxw);
                    maxw = better ? w : maxw;
                    best = better ? C.w : best;
                    T = T * (1.0f - a);

                    A = A2; B = B2; C = C2;
                }
            }
        }
        if (__syncthreads_and(T < 1e-4f)) break;
    }

    if (!producer) {
        int pix = y * IMW + x;
        out[0*HW + pix] = cr;
        out[1*HW + pix] = cg;
        out[2*HW + pix] = cb;
        out[3*HW + pix] = invd;
        out[4*HW + pix] = (maxw > 0.0f) ? best : -1.0f;
    }
}

extern "C" void kernel_launch(void* const* d_in, const int* in_sizes, int n_in,
                              void* d_out, int out_size)
{
    (void)in_sizes; (void)n_in; (void)out_size;
    const float* means3D   = (const float*)d_in[0];
    const float* opacities = (const float*)d_in[2];
    const float* dc        = (const float*)d_in[3];
    const float* shs       = (const float*)d_in[4];
    const float* scales    = (const float*)d_in[5];
    const float* rotations = (const float*)d_in[6];
    const float* viewm     = (const float*)d_in[7];
    const float* projm     = (const float*)d_in[8];
    float* out = (float*)d_out;

    fused_kernel<<<GRID, NTHREADS>>>(means3D, opacities, dc, shs, scales,
                                     rotations, viewm, projm, out);
}

// round 16
// speedup vs baseline: 1.1360x; 1.0602x over previous
#include <cuda_runtime.h>
#include <cuda_bf16.h>
#include <math.h>

#define NG 2048
#define IMW 128
#define IMH 128
#define HW (IMW*IMH)
#define GRID 128
#define NTHREADS 256

#define TANFOVX 0.5f
#define TANFOVY 0.5f
#define FOCAL_X (IMW / (2.0f * TANFOVX))   // 128
#define FOCAL_Y (IMH / (2.0f * TANFOVY))   // 128
#define FARZ 1e10f

#define SH_C0 0.28209479177387814f
#define SH_C1 0.4886025119029199f
#define SH_C2_0 1.0925484305920792f
#define SH_C2_1 (-1.0925484305920792f)
#define SH_C2_2 0.31539156525252005f
#define SH_C2_3 (-1.0925484305920792f)
#define SH_C2_4 0.5462742152960396f
#define SH_C3_0 (-0.5900435899266435f)
#define SH_C3_1 2.890611442640554f
#define SH_C3_2 (-0.4570457994644657f)
#define SH_C3_3 0.3731763325901154f
#define SH_C3_4 (-0.4570457994644657f)
#define SH_C3_5 1.445305721320277f
#define SH_C3_6 (-0.5900435899266435f)

// Unsorted packed records
__device__ float4 g_upack0[NG];  // px, py, na(-0.5ca), nb(-cb)
__device__ float4 g_upack1[NG];  // nc(-0.5cc), op, cr, cg
__device__ float4 g_upack2[NG];  // cb(blue), invd, rad, id
__device__ float  g_depth[NG];
// Depth-sorted packed records
__device__ float4 g_pack0[NG];
__device__ float4 g_pack1[NG];
__device__ float4 g_pack2[NG];

// Monotone ticket grid barrier (replay-safe: target derived from ticket).
__device__ unsigned int g_bar_ctr = 0;

__device__ __forceinline__ void grid_barrier()
{
    __syncthreads();
    if (threadIdx.x == 0) {
        __threadfence();
        unsigned int ticket = atomicAdd(&g_bar_ctr, 1u);
        unsigned int target = (ticket / GRID + 1u) * GRID;
        unsigned int v;
        do {
            asm volatile("ld.acquire.gpu.u32 %0, [%1];" : "=r"(v) : "l"(&g_bar_ctr));
        } while (v < target);
    }
    __syncthreads();
}

#define CHUNK 512
#define NCHUNK (NG / CHUNK)   // 4

// Dynamic smem layout: A[2][512] | B[2][512] | C[2][512]  = 49152 B exactly
#define DSMEM_BYTES (3 * 2 * CHUNK * 16)

__global__ void __launch_bounds__(NTHREADS) fused_kernel(
    const float* __restrict__ means3D,
    const float* __restrict__ opacities,
    const float* __restrict__ dc,
    const float* __restrict__ shs,
    const float* __restrict__ scales,
    const float* __restrict__ rotations,
    const float* __restrict__ Vm,
    const float* __restrict__ Pm,
    float* __restrict__ out)
{
    extern __shared__ float4 dyn[];
    float4* sA = dyn;                 // [2][CHUNK]
    float4* sB = dyn + 2 * CHUNK;     // [2][CHUNK]
    float4* sC = dyn + 4 * CHUNK;     // [2][CHUNK]

    __shared__ float sd[NG];          // phase 2 (8KB, static)
    __shared__ int   sw[2][16];       // counts [buf][group r*4 + producer warp]

    int tid  = threadIdx.x;
    int warp = tid >> 5;
    int lane = tid & 31;

    // ========================================================
    // Phase 1: preprocess. threads 0..15 own one gaussian each
    // ========================================================
    if (tid < 16) {
        int n = blockIdx.x * 16 + tid;

        float m0 = means3D[3*n+0], m1 = means3D[3*n+1], m2 = means3D[3*n+2];

        float pv0 = m0*Vm[0] + m1*Vm[4] + m2*Vm[8]  + Vm[12];
        float pv1 = m0*Vm[1] + m1*Vm[5] + m2*Vm[9]  + Vm[13];
        float pv2 = m0*Vm[2] + m1*Vm[6] + m2*Vm[10] + Vm[14];

        float ph0 = m0*Pm[0] + m1*Pm[4] + m2*Pm[8]  + Pm[12];
        float ph1 = m0*Pm[1] + m1*Pm[5] + m2*Pm[9]  + Pm[13];
        float ph3 = m0*Pm[3] + m1*Pm[7] + m2*Pm[11] + Pm[15];
        float invw = 1.0f / (ph3 + 1e-7f);
        float px = ((ph0*invw + 1.0f) * IMW - 1.0f) * 0.5f;
        float py = ((ph1*invw + 1.0f) * IMH - 1.0f) * 0.5f;

        float tz = pv2;
        float limx = 1.3f * TANFOVX, limy = 1.3f * TANFOVY;
        float tx = fminf(fmaxf(pv0 / tz, -limx), limx) * tz;
        float ty = fminf(fmaxf(pv1 / tz, -limy), limy) * tz;

        float qr = rotations[4*n+0], qx = rotations[4*n+1],
              qy = rotations[4*n+2], qz = rotations[4*n+3];
        float R00 = 1.f - 2.f*(qy*qy + qz*qz);
        float R01 = 2.f*(qx*qy - qr*qz);
        float R02 = 2.f*(qx*qz + qr*qy);
        float R10 = 2.f*(qx*qy + qr*qz);
        float R11 = 1.f - 2.f*(qx*qx + qz*qz);
        float R12 = 2.f*(qy*qz - qr*qx);
        float R20 = 2.f*(qx*qz - qr*qy);
        float R21 = 2.f*(qy*qz + qr*qx);
        float R22 = 1.f - 2.f*(qx*qx + qy*qy);

        float s0 = scales[3*n+0], s1 = scales[3*n+1], s2 = scales[3*n+2];
        float M00=R00*s0, M01=R01*s1, M02=R02*s2;
        float M10=R10*s0, M11=R11*s1, M12=R12*s2;
        float M20=R20*s0, M21=R21*s1, M22=R22*s2;
        float S00 = M00*M00 + M01*M01 + M02*M02;
        float S01 = M00*M10 + M01*M11 + M02*M12;
        float S02 = M00*M20 + M01*M21 + M02*M22;
        float S11 = M10*M10 + M11*M11 + M12*M12;
        float S12 = M10*M20 + M11*M21 + M12*M22;
        float S22 = M20*M20 + M21*M21 + M22*M22;

        float itz = 1.0f / tz;
        float J00 = FOCAL_X * itz;
        float J02 = -FOCAL_X * tx * itz * itz;
        float J11 = FOCAL_Y * itz;
        float J12 = -FOCAL_Y * ty * itz * itz;

        float T00 = J00*Vm[0] + J02*Vm[2];
        float T01 = J00*Vm[4] + J02*Vm[6];
        float T02 = J00*Vm[8] + J02*Vm[10];
        float T10 = J11*Vm[1] + J12*Vm[2];
        float T11 = J11*Vm[5] + J12*Vm[6];
        float T12 = J11*Vm[9] + J12*Vm[10];

        float A00 = T00*S00 + T01*S01 + T02*S02;
        float A01 = T00*S01 + T01*S11 + T02*S12;
        float A02 = T00*S02 + T01*S12 + T02*S22;
        float B00 = T10*S00 + T11*S01 + T12*S02;
        float B01 = T10*S01 + T11*S11 + T12*S12;
        float B02 = T10*S02 + T11*S12 + T12*S22;

        float cov00 = A00*T00 + A01*T01 + A02*T02;
        float cov01 = A00*T10 + A01*T11 + A02*T12;
        float cov11 = B00*T10 + B01*T11 + B02*T12;

        float a = cov00 + 0.3f;
        float b = cov01;
        float c = cov11 + 0.3f;
        float det = a*c - b*b;
        bool valid = (tz > 0.2f) && (det > 0.0f);
        float det_inv = (det > 0.0f) ? (1.0f / det) : 0.0f;

        float mid = 0.5f * (a + c);
        float lam1 = mid + sqrtf(fmaxf(0.1f, mid*mid - det));
        float radius = ceilf(3.0f * sqrtf(lam1));

        float invn = rsqrtf(m0*m0 + m1*m1 + m2*m2);
        float dX = m0*invn, dY = m1*invn, dZ = m2*invn;
        float xx = dX*dX, yy = dY*dY, zz = dZ*dZ;
        float xy = dX*dY, yz = dY*dZ, xz = dX*dZ;

        float col[3];
        #pragma unroll
        for (int ch = 0; ch < 3; ch++) {
            const float* sh = shs + (size_t)n*45 + ch;
            float res = SH_C0 * dc[3*n + ch];
            res += -SH_C1 * dY * sh[0*3] + SH_C1 * dZ * sh[1*3] - SH_C1 * dX * sh[2*3];
            res += SH_C2_0 * xy * sh[3*3] + SH_C2_1 * yz * sh[4*3]
                 + SH_C2_2 * (2.f*zz - xx - yy) * sh[5*3]
                 + SH_C2_3 * xz * sh[6*3] + SH_C2_4 * (xx - yy) * sh[7*3];
            res += SH_C3_0 * dY * (3.f*xx - yy) * sh[8*3]
                 + SH_C3_1 * xy * dZ * sh[9*3]
                 + SH_C3_2 * dY * (4.f*zz - xx - yy) * sh[10*3]
                 + SH_C3_3 * dZ * (2.f*zz - 3.f*xx - 3.f*yy) * sh[11*3]
                 + SH_C3_4 * dX * (4.f*zz - xx - yy) * sh[12*3]
                 + SH_C3_5 * dZ * (xx - yy) * sh[13*3]
                 + SH_C3_6 * dX * (xx - 3.f*yy) * sh[14*3];
            col[ch] = fmaxf(res + 0.5f, 0.0f);
        }

        float depth = valid ? tz : FARZ;
        float rad   = valid ? radius : 0.0f;

        float ca = c * det_inv, cbq = -b * det_inv, ccq = a * det_inv;
        g_upack0[n] = make_float4(px, py, -0.5f * ca, -cbq);
        g_upack1[n] = make_float4(-0.5f * ccq, opacities[n], col[0], col[1]);
        g_upack2[n] = make_float4(col[2], 1.0f / depth, rad, (float)n);
        g_depth[n]  = depth;

        out[5*HW + n] = rad;   // radii
    }

    grid_barrier();

    // ========================================================
    // Phase 2: stable rank-count argsort + scatter.
    // 16 gaussians/block over 8 warps -> 2 rounds each.
    // ========================================================
    #pragma unroll
    for (int i = tid; i < NG; i += NTHREADS) sd[i] = g_depth[i];
    __syncthreads();

    #pragma unroll
    for (int r = 0; r < 2; r++) {
        int gi = blockIdx.x * 16 + warp * 2 + r;
        float di = sd[gi];
        int cnt = 0;
        #pragma unroll 8
        for (int j = lane; j < NG; j += 32) {
            float dj = sd[j];
            cnt += (dj < di) || (dj == di && j < gi);
        }
        #pragma unroll
        for (int o = 16; o > 0; o >>= 1) cnt += __shfl_down_sync(0xffffffffu, cnt, o);
        if (lane == 0) {
            g_pack0[cnt] = g_upack0[gi];
            g_pack1[cnt] = g_upack1[gi];
            g_pack2[cnt] = g_upack2[gi];
        }
    }

    grid_barrier();

    // ========================================================
    // Phase 3: warp-specialized raster, CHUNK=512, NCHUNK=4.
    // Warps 0-3: consumers; warps 4-7: producers (4 records each).
    // ========================================================
    bool producer = (tid >= 128);
    int bx = blockIdx.x & 7;
    int by = blockIdx.x >> 3;

    float tx0 = (float)(bx * 16);
    float tx1 = tx0 + 15.0f;
    float ty0 = (float)(by * 8);
    float ty1 = ty0 + 7.0f;

    int lx = tid & 15;
    int ly = (tid >> 4) & 7;
    int x = bx * 16 + lx;
    int y = by * 8 + ly;
    float fx = (float)x, fy = (float)y;

    float T = producer ? 0.0f : 1.0f;   // producers always vote "done"
    float cr = 0.f, cg = 0.f, cb = 0.f, invd = 0.f;
    float maxw = 0.f;
    float best = -1.0f;

    int ptid = tid - 128;   // 0..127
    int pw   = warp - 4;    // 0..3

    // producer fill: 4 record-groups of 128, stable order preserved
    auto fill = [&](int c, int b) {
        float4 pa[4], pb[4], pc[4];
        #pragma unroll
        for (int r = 0; r < 4; r++) {
            int e = c * CHUNK + r * 128 + ptid;
            pa[r] = g_pack0[e]; pb[r] = g_pack1[e]; pc[r] = g_pack2[e];
        }
        bool k[4]; unsigned int m[4];
        #pragma unroll
        for (int r = 0; r < 4; r++) {
            float rad = pc[r].z;
            k[r] = (rad > 0.0f) &&
                   (pa[r].x >= tx0 - rad) && (pa[r].x <= tx1 + rad) &&
                   (pa[r].y >= ty0 - rad) && (pa[r].y <= ty1 + rad);
            m[r] = __ballot_sync(0xffffffffu, k[r]);
            if (lane == 0) sw[b][r*4 + pw] = __popc(m[r]);
        }
        asm volatile("bar.sync 8, 128;" ::: "memory");   // producers only

        int base = 0;
        unsigned int below = (1u << lane) - 1u;
        float4* A = sA + b * CHUNK;
        float4* B = sB + b * CHUNK;
        float4* C = sC + b * CHUNK;
        #pragma unroll
        for (int r = 0; r < 4; r++) {
            int c0 = sw[b][r*4+0], c1 = sw[b][r*4+1], c2 = sw[b][r*4+2], c3 = sw[b][r*4+3];
            int off = base;
            if (pw > 0) off += c0;
            if (pw > 1) off += c1;
            if (pw > 2) off += c2;
            if (k[r]) {
                int pos = off + __popc(m[r] & below);
                A[pos] = pa[r]; B[pos] = pb[r]; C[pos] = pc[r];
            }
            base += c0 + c1 + c2 + c3;
        }
    };

    if (producer) fill(0, 0);
    __syncthreads();

    for (int c = 0; c < NCHUNK; c++) {
        int buf = c & 1;

        if (producer) {
            if (c + 1 < NCHUNK) fill(c + 1, buf ^ 1);
        } else {
            int total = 0;
            #pragma unroll
            for (int i = 0; i < 16; i++) total += sw[buf][i];
            if (T >= 1e-4f && total > 0) {
                const float4* A_ = sA + buf * CHUNK;
                const float4* B_ = sB + buf * CHUNK;
                const float4* C_ = sC + buf * CHUNK;
                float4 A = A_[0];
                float4 B = B_[0];
                float4 C = C_[0];
                for (int g = 0; g < total; g++) {
                    int gn = min(g + 1, total - 1);
                    float4 A2 = A_[gn];
                    float4 B2 = B_[gn];
                    float4 C2 = C_[gn];

                    float dx = fx - A.x;
                    float dy = fy - A.y;
                    float r  = C.z;
                    float power = fmaf(A.z, dx*dx, fmaf(B.x, dy*dy, A.w*(dx*dy)));
                    float alpha = fminf(0.99f, B.y * __expf(power));
                    bool ok = (fmaxf(fabsf(dx), fabsf(dy)) <= r) &
                              (power <= 0.0f) & (alpha >= (1.0f/255.0f));
                    float a = ok ? alpha : 0.0f;
                    float w = a * T;
                    cr   += w * B.z;
                    cg   += w * B.w;
                    cb   += w * C.x;
                    invd += w * C.y;
                    bool better = (w > maxw);
                    maxw = better ? w : maxw;
                    best = better ? C.w : best;
                    T = T * (1.0f - a);

                    A = A2; B = B2; C = C2;
                }
            }
        }
        if (__syncthreads_and(T < 1e-4f)) break;
    }

    if (!producer) {
        int pix = y * IMW + x;
        out[0*HW + pix] = cr;
        out[1*HW + pix] = cg;
        out[2*HW + pix] = cb;
        out[3*HW + pix] = invd;
        out[4*HW + pix] = (maxw > 0.0f) ? best : -1.0f;
    }
}

extern "C" void kernel_launch(void* const* d_in, const int* in_sizes, int n_in,
                              void* d_out, int out_size)
{
    (void)in_sizes; (void)n_in; (void)out_size;
    const float* means3D   = (const float*)d_in[0];
    const float* opacities = (const float*)d_in[2];
    const float* dc        = (const float*)d_in[3];
    const float* shs       = (const float*)d_in[4];
    const float* scales    = (const float*)d_in[5];
    const float* rotations = (const float*)d_in[6];
    const float* viewm     = (const float*)d_in[7];
    const float* projm     = (const float*)d_in[8];
    float* out = (float*)d_out;

    // Host-side attribute set: not a stream op, graph-capture legal.
    // Opt in to 48KB dynamic smem alongside the 8.3KB static.
    cudaFuncSetAttribute(fused_kernel,
                         cudaFuncAttributeMaxDynamicSharedMemorySize,
                         DSMEM_BYTES);

    fused_kernel<<<GRID, NTHREADS, DSMEM_BYTES>>>(means3D, opacities, dc, shs,
                                                  scales, rotations, viewm,
                                                  projm, out);
}

// round 17
// speedup vs baseline: 1.1458x; 1.0087x over previous
#include <cuda_runtime.h>
#include <cuda_bf16.h>
#include <math.h>

#define NG 2048
#define IMW 128
#define IMH 128
#define HW (IMW*IMH)
#define GRID 128
#define NTHREADS 256

#define TANFOVX 0.5f
#define TANFOVY 0.5f
#define FOCAL_X (IMW / (2.0f * TANFOVX))   // 128
#define FOCAL_Y (IMH / (2.0f * TANFOVY))   // 128
#define FARZ 1e10f

#define SH_C0 0.28209479177387814f
#define SH_C1 0.4886025119029199f
#define SH_C2_0 1.0925484305920792f
#define SH_C2_1 (-1.0925484305920792f)
#define SH_C2_2 0.31539156525252005f
#define SH_C2_3 (-1.0925484305920792f)
#define SH_C2_4 0.5462742152960396f
#define SH_C3_0 (-0.5900435899266435f)
#define SH_C3_1 2.890611442640554f
#define SH_C3_2 (-0.4570457994644657f)
#define SH_C3_3 0.3731763325901154f
#define SH_C3_4 (-0.4570457994644657f)
#define SH_C3_5 1.445305721320277f
#define SH_C3_6 (-0.5900435899266435f)

// Unsorted packed records
__device__ float4 g_upack0[NG];  // px, py, na(-0.5ca), nb(-cb)
__device__ float4 g_upack1[NG];  // nc(-0.5cc), op, cr, cg
__device__ float4 g_upack2[NG];  // cb(blue), invd, rad, id
__device__ float  g_depth[NG];
// Depth-sorted packed records
__device__ float4 g_pack0[NG];
__device__ float4 g_pack1[NG];
__device__ float4 g_pack2[NG];

// Monotone ticket grid barrier (replay-safe: target derived from ticket).
__device__ unsigned int g_bar_ctr = 0;

__device__ __forceinline__ void grid_barrier()
{
    __syncthreads();
    if (threadIdx.x == 0) {
        __threadfence();
        unsigned int ticket = atomicAdd(&g_bar_ctr, 1u);
        unsigned int target = (ticket / GRID + 1u) * GRID;
        unsigned int v;
        do {
            asm volatile("ld.acquire.gpu.u32 %0, [%1];" : "=r"(v) : "l"(&g_bar_ctr));
        } while (v < target);
    }
    __syncthreads();
}

#define CHUNK 1024
#define NCHUNK (NG / CHUNK)   // 2

// Dynamic smem: A[2][1024] | B[2][1024] | C[2][1024] = 98304 B
#define DSMEM_BYTES (3 * 2 * CHUNK * 16)

__global__ void __launch_bounds__(NTHREADS) fused_kernel(
    const float* __restrict__ means3D,
    const float* __restrict__ opacities,
    const float* __restrict__ dc,
    const float* __restrict__ shs,
    const float* __restrict__ scales,
    const float* __restrict__ rotations,
    const float* __restrict__ Vm,
    const float* __restrict__ Pm,
    float* __restrict__ out)
{
    extern __shared__ float4 dyn[];
    float4* sA = dyn;                 // [2][CHUNK]
    float4* sB = dyn + 2 * CHUNK;     // [2][CHUNK]
    float4* sC = dyn + 4 * CHUNK;     // [2][CHUNK]

    __shared__ float sd[NG];          // phase 2 (8KB, static)
    __shared__ int   sw[2][32];       // counts [buf][half*16 + group*4 + pw]
    __shared__ int   sw_total[2];     // survivor count per buffer

    int tid  = threadIdx.x;
    int warp = tid >> 5;
    int lane = tid & 31;

    // ========================================================
    // Phase 1: preprocess. threads 0..15 own one gaussian each
    // ========================================================
    if (tid < 16) {
        int n = blockIdx.x * 16 + tid;

        float m0 = means3D[3*n+0], m1 = means3D[3*n+1], m2 = means3D[3*n+2];

        float pv0 = m0*Vm[0] + m1*Vm[4] + m2*Vm[8]  + Vm[12];
        float pv1 = m0*Vm[1] + m1*Vm[5] + m2*Vm[9]  + Vm[13];
        float pv2 = m0*Vm[2] + m1*Vm[6] + m2*Vm[10] + Vm[14];

        float ph0 = m0*Pm[0] + m1*Pm[4] + m2*Pm[8]  + Pm[12];
        float ph1 = m0*Pm[1] + m1*Pm[5] + m2*Pm[9]  + Pm[13];
        float ph3 = m0*Pm[3] + m1*Pm[7] + m2*Pm[11] + Pm[15];
        float invw = 1.0f / (ph3 + 1e-7f);
        float px = ((ph0*invw + 1.0f) * IMW - 1.0f) * 0.5f;
        float py = ((ph1*invw + 1.0f) * IMH - 1.0f) * 0.5f;

        float tz = pv2;
        float limx = 1.3f * TANFOVX, limy = 1.3f * TANFOVY;
        float tx = fminf(fmaxf(pv0 / tz, -limx), limx) * tz;
        float ty = fminf(fmaxf(pv1 / tz, -limy), limy) * tz;

        float qr = rotations[4*n+0], qx = rotations[4*n+1],
              qy = rotations[4*n+2], qz = rotations[4*n+3];
        float R00 = 1.f - 2.f*(qy*qy + qz*qz);
        float R01 = 2.f*(qx*qy - qr*qz);
        float R02 = 2.f*(qx*qz + qr*qy);
        float R10 = 2.f*(qx*qy + qr*qz);
        float R11 = 1.f - 2.f*(qx*qx + qz*qz);
        float R12 = 2.f*(qy*qz - qr*qx);
        float R20 = 2.f*(qx*qz - qr*qy);
        float R21 = 2.f*(qy*qz + qr*qx);
        float R22 = 1.f - 2.f*(qx*qx + qy*qy);

        float s0 = scales[3*n+0], s1 = scales[3*n+1], s2 = scales[3*n+2];
        float M00=R00*s0, M01=R01*s1, M02=R02*s2;
        float M10=R10*s0, M11=R11*s1, M12=R12*s2;
        float M20=R20*s0, M21=R21*s1, M22=R22*s2;
        float S00 = M00*M00 + M01*M01 + M02*M02;
        float S01 = M00*M10 + M01*M11 + M02*M12;
        float S02 = M00*M20 + M01*M21 + M02*M22;
        float S11 = M10*M10 + M11*M11 + M12*M12;
        float S12 = M10*M20 + M11*M21 + M12*M22;
        float S22 = M20*M20 + M21*M21 + M22*M22;

        float itz = 1.0f / tz;
        float J00 = FOCAL_X * itz;
        float J02 = -FOCAL_X * tx * itz * itz;
        float J11 = FOCAL_Y * itz;
        float J12 = -FOCAL_Y * ty * itz * itz;

        float T00 = J00*Vm[0] + J02*Vm[2];
        float T01 = J00*Vm[4] + J02*Vm[6];
        float T02 = J00*Vm[8] + J02*Vm[10];
        float T10 = J11*Vm[1] + J12*Vm[2];
        float T11 = J11*Vm[5] + J12*Vm[6];
        float T12 = J11*Vm[9] + J12*Vm[10];

        float A00 = T00*S00 + T01*S01 + T02*S02;
        float A01 = T00*S01 + T01*S11 + T02*S12;
        float A02 = T00*S02 + T01*S12 + T02*S22;
        float B00 = T10*S00 + T11*S01 + T12*S02;
        float B01 = T10*S01 + T11*S11 + T12*S12;
        float B02 = T10*S02 + T11*S12 + T12*S22;

        float cov00 = A00*T00 + A01*T01 + A02*T02;
        float cov01 = A00*T10 + A01*T11 + A02*T12;
        float cov11 = B00*T10 + B01*T11 + B02*T12;

        float a = cov00 + 0.3f;
        float b = cov01;
        float c = cov11 + 0.3f;
        float det = a*c - b*b;
        bool valid = (tz > 0.2f) && (det > 0.0f);
        float det_inv = (det > 0.0f) ? (1.0f / det) : 0.0f;

        float mid = 0.5f * (a + c);
        float lam1 = mid + sqrtf(fmaxf(0.1f, mid*mid - det));
        float radius = ceilf(3.0f * sqrtf(lam1));

        float invn = rsqrtf(m0*m0 + m1*m1 + m2*m2);
        float dX = m0*invn, dY = m1*invn, dZ = m2*invn;
        float xx = dX*dX, yy = dY*dY, zz = dZ*dZ;
        float xy = dX*dY, yz = dY*dZ, xz = dX*dZ;

        float col[3];
        #pragma unroll
        for (int ch = 0; ch < 3; ch++) {
            const float* sh = shs + (size_t)n*45 + ch;
            float res = SH_C0 * dc[3*n + ch];
            res += -SH_C1 * dY * sh[0*3] + SH_C1 * dZ * sh[1*3] - SH_C1 * dX * sh[2*3];
            res += SH_C2_0 * xy * sh[3*3] + SH_C2_1 * yz * sh[4*3]
                 + SH_C2_2 * (2.f*zz - xx - yy) * sh[5*3]
                 + SH_C2_3 * xz * sh[6*3] + SH_C2_4 * (xx - yy) * sh[7*3];
            res += SH_C3_0 * dY * (3.f*xx - yy) * sh[8*3]
                 + SH_C3_1 * xy * dZ * sh[9*3]
                 + SH_C3_2 * dY * (4.f*zz - xx - yy) * sh[10*3]
                 + SH_C3_3 * dZ * (2.f*zz - 3.f*xx - 3.f*yy) * sh[11*3]
                 + SH_C3_4 * dX * (4.f*zz - xx - yy) * sh[12*3]
                 + SH_C3_5 * dZ * (xx - yy) * sh[13*3]
                 + SH_C3_6 * dX * (xx - 3.f*yy) * sh[14*3];
            col[ch] = fmaxf(res + 0.5f, 0.0f);
        }

        float depth = valid ? tz : FARZ;
        float rad   = valid ? radius : 0.0f;

        float ca = c * det_inv, cbq = -b * det_inv, ccq = a * det_inv;
        g_upack0[n] = make_float4(px, py, -0.5f * ca, -cbq);
        g_upack1[n] = make_float4(-0.5f * ccq, opacities[n], col[0], col[1]);
        g_upack2[n] = make_float4(col[2], 1.0f / depth, rad, (float)n);
        g_depth[n]  = depth;

        out[5*HW + n] = rad;   // radii
    }

    grid_barrier();

    // ========================================================
    // Phase 2: stable rank-count argsort + scatter.
    // ========================================================
    #pragma unroll
    for (int i = tid; i < NG; i += NTHREADS) sd[i] = g_depth[i];
    __syncthreads();

    #pragma unroll
    for (int r = 0; r < 2; r++) {
        int gi = blockIdx.x * 16 + warp * 2 + r;
        float di = sd[gi];
        int cnt = 0;
        #pragma unroll 8
        for (int j = lane; j < NG; j += 32) {
            float dj = sd[j];
            cnt += (dj < di) || (dj == di && j < gi);
        }
        #pragma unroll
        for (int o = 16; o > 0; o >>= 1) cnt += __shfl_down_sync(0xffffffffu, cnt, o);
        if (lane == 0) {
            g_pack0[cnt] = g_upack0[gi];
            g_pack1[cnt] = g_upack1[gi];
            g_pack2[cnt] = g_upack2[gi];
        }
    }

    grid_barrier();

    // ========================================================
    // Phase 3: warp-specialized raster, CHUNK=1024, NCHUNK=2.
    // Warps 0-3: consumers; warps 4-7: producers.
    // ========================================================
    bool producer = (tid >= 128);
    int bx = blockIdx.x & 7;
    int by = blockIdx.x >> 3;

    float tx0 = (float)(bx * 16);
    float tx1 = tx0 + 15.0f;
    float ty0 = (float)(by * 8);
    float ty1 = ty0 + 7.0f;

    int lx = tid & 15;
    int ly = (tid >> 4) & 7;
    int x = bx * 16 + lx;
    int y = by * 8 + ly;
    float fx = (float)x, fy = (float)y;

    float T = producer ? 0.0f : 1.0f;   // producers always vote "done"
    float cr = 0.f, cg = 0.f, cb = 0.f, invd = 0.f;
    float maxw = 0.f;
    float best = -1.0f;

    int ptid = tid - 128;   // 0..127
    int pw   = warp - 4;    // 0..3

    // half-fill: 4 record-groups of 128 from src offset; scatter starting at
    // 'base0'; returns new base. Stable depth order preserved.
    auto half_fill = [&](int src, int b, int halfIdx, int base0) -> int {
        float4 pa[4], pb[4], pc[4];
        #pragma unroll
        for (int r = 0; r < 4; r++) {
            int e = src + r * 128 + ptid;
            pa[r] = g_pack0[e]; pb[r] = g_pack1[e]; pc[r] = g_pack2[e];
        }
        bool k[4]; unsigned int m[4];
        #pragma unroll
        for (int r = 0; r < 4; r++) {
            float rad = pc[r].z;
            k[r] = (rad > 0.0f) &&
                   (pa[r].x >= tx0 - rad) && (pa[r].x <= tx1 + rad) &&
                   (pa[r].y >= ty0 - rad) && (pa[r].y <= ty1 + rad);
            m[r] = __ballot_sync(0xffffffffu, k[r]);
            if (lane == 0) sw[b][halfIdx*16 + r*4 + pw] = __popc(m[r]);
        }
        asm volatile("bar.sync 8, 128;" ::: "memory");   // producers only

        int base = base0;
        unsigned int below = (1u << lane) - 1u;
        float4* A = sA + b * CHUNK;
        float4* B = sB + b * CHUNK;
        float4* C = sC + b * CHUNK;
        #pragma unroll
        for (int r = 0; r < 4; r++) {
            int c0 = sw[b][halfIdx*16 + r*4+0], c1 = sw[b][halfIdx*16 + r*4+1];
            int c2 = sw[b][halfIdx*16 + r*4+2], c3 = sw[b][halfIdx*16 + r*4+3];
            int off = base;
            if (pw > 0) off += c0;
            if (pw > 1) off += c1;
            if (pw > 2) off += c2;
            if (k[r]) {
                int pos = off + __popc(m[r] & below);
                A[pos] = pa[r]; B[pos] = pb[r]; C[pos] = pc[r];
            }
            base += c0 + c1 + c2 + c3;
        }
        return base;
    };

    auto fill = [&](int c, int b) {
        int base = half_fill(c * CHUNK, b, 0, 0);
        base = half_fill(c * CHUNK + 512, b, 1, base);
        if (ptid == 0) sw_total[b] = base;
    };

    if (producer) fill(0, 0);
    __syncthreads();

    for (int c = 0; c < NCHUNK; c++) {
        int buf = c & 1;

        if (producer) {
            if (c + 1 < NCHUNK) fill(c + 1, buf ^ 1);
        } else {
            int total = sw_total[buf];
            if (T >= 1e-4f && total > 0) {
                const float4* A_ = sA + buf * CHUNK;
                const float4* B_ = sB + buf * CHUNK;
                const float4* C_ = sC + buf * CHUNK;
                float4 A = A_[0];
                float4 B = B_[0];
                float4 C = C_[0];
                for (int g = 0; g < total; g++) {
                    int gn = min(g + 1, total - 1);
                    float4 A2 = A_[gn];
                    float4 B2 = B_[gn];
                    float4 C2 = C_[gn];

                    float dx = fx - A.x;
                    float dy = fy - A.y;
                    float r  = C.z;
                    float power = fmaf(A.z, dx*dx, fmaf(B.x, dy*dy, A.w*(dx*dy)));
                    float alpha = fminf(0.99f, B.y * __expf(power));
                    bool ok = (fmaxf(fabsf(dx), fabsf(dy)) <= r) &
                              (power <= 0.0f) & (alpha >= (1.0f/255.0f));
                    float a = ok ? alpha : 0.0f;
                    float w = a * T;
                    cr   += w * B.z;
                    cg   += w * B.w;
                    cb   += w * C.x;
                    invd += w * C.y;
                    bool better = (w > maxw);
                    maxw = better ? w : maxw;
                    best = better ? C.w : best;
                    T = T * (1.0f - a);

                    A = A2; B = B2; C = C2;
                }
            }
        }
        if (__syncthreads_and(T < 1e-4f)) break;
    }

    if (!producer) {
        int pix = y * IMW + x;
        out[0*HW + pix] = cr;
        out[1*HW + pix] = cg;
        out[2*HW + pix] = cb;
        out[3*HW + pix] = invd;
        out[4*HW + pix] = (maxw > 0.0f) ? best : -1.0f;
    }
}

extern "C" void kernel_launch(void* const* d_in, const int* in_sizes, int n_in,
                              void* d_out, int out_size)
{
    (void)in_sizes; (void)n_in; (void)out_size;
    const float* means3D   = (const float*)d_in[0];
    const float* opacities = (const float*)d_in[2];
    const float* dc        = (const float*)d_in[3];
    const float* shs       = (const float*)d_in[4];
    const float* scales    = (const float*)d_in[5];
    const float* rotations = (const float*)d_in[6];
    const float* viewm     = (const float*)d_in[7];
    const float* projm     = (const float*)d_in[8];
    float* out = (float*)d_out;

    // Host-side attribute (not a stream op; graph-capture legal):
    // opt in to 96KB dynamic smem alongside ~8.4KB static.
    cudaFuncSetAttribute(fused_kernel,
                         cudaFuncAttributeMaxDynamicSharedMemorySize,
                         DSMEM_BYTES);

    fused_kernel<<<GRID, NTHREADS, DSMEM_BYTES>>>(means3D, opacities, dc, shs,
                                                  scales, rotations, viewm,
                                                  projm, out);
}